// round 2
// baseline (speedup 1.0000x reference)
#include <cuda_runtime.h>

#define HID 64
#define MAX_OBJ 100000
#define MAX_GRAPHS 256

typedef unsigned long long ull;

__device__ float g_obj[MAX_OBJ * HID];
__device__ float g_agg[MAX_OBJ * HID];
__device__ int   g_deg[6 * MAX_OBJ];
__device__ float g_const[64 + 128 + 192];
__device__ float g_pooled[MAX_GRAPHS * HID];

__device__ __forceinline__ void fma2(ull& d, ull a, ull b) {
    asm("fma.rn.f32x2 %0, %1, %2, %0;" : "+l"(d) : "l"(a), "l"(b));
}
__device__ __forceinline__ ull pack2(float v) {
    ull r; asm("mov.b64 %0, {%1, %2};" : "=l"(r) : "f"(v), "f"(v)); return r;
}
__device__ __forceinline__ float2 unpack2(ull v) {
    float2 f; asm("mov.b64 {%0, %1}, %2;" : "=f"(f.x), "=f"(f.y) : "l"(v)); return f;
}

// 64-col (atom) tile GEMM: Xs transposed [K rows][64 atoms], row stride 66.
// W row-major [K][N] streamed via Ws in 16-row tiles. 128 threads:
// cg = tid&15 owns N/16 output cols, ag = tid>>4 owns 8 atoms (4 f32x2 pairs).
// Ends with a barrier so the caller may overwrite Xs.
template<int K, int N>
__device__ __forceinline__ void gemm_phase(const float* __restrict__ Wg,
                                           const float* Xs, float* Ws,
                                           int a0, int cg, ull* acc) {
    constexpr int NC = N / 16;
    #pragma unroll
    for (int i = 0; i < NC * 4; i++) acc[i] = 0ull;

    for (int kt = 0; kt < K; kt += 16) {
        __syncthreads();
        #pragma unroll
        for (int idx = 0; idx < 16 * N; idx += 512) {
            int t = idx + threadIdx.x * 4;
            *(float4*)(Ws + t) = *(const float4*)(Wg + kt * N + t);
        }
        __syncthreads();
        #pragma unroll
        for (int k = 0; k < 16; k++) {
            const float* xrow = Xs + (kt + k) * 66 + a0;
            ull xv[4];
            #pragma unroll
            for (int p = 0; p < 4; p++) xv[p] = *(const ull*)(xrow + 2 * p);
            float wv[NC];
            #pragma unroll
            for (int c = 0; c < NC; c += 4)
                *(float4*)(wv + c) = *(const float4*)(Ws + k * N + cg * NC + c);
            #pragma unroll
            for (int c = 0; c < NC; c++) {
                ull wp = pack2(wv[c]);
                #pragma unroll
                for (int p = 0; p < 4; p++) fma2(acc[c * 4 + p], xv[p], wp);
            }
        }
    }
    __syncthreads();
}

// Fused predicate kernel: gather -> MLP -> scatter-add. 64 atoms per block.
template<int R>
__global__ void __launch_bounds__(128)
pred_kernel(const int* __restrict__ ei, int nAtoms,
            const float* __restrict__ W1, const float* __restrict__ b1,
            const float* __restrict__ W2, const float* __restrict__ b2) {
    constexpr int D = 64 * R;
    constexpr int NC = D / 16;
    extern __shared__ float smem[];
    float* Xs = smem;                 // D*66
    float* Ws = Xs + D * 66;          // 16*D
    int*   es = (int*)(Ws + 16 * D);  // R*64

    const int tid  = threadIdx.x;
    const int base = blockIdx.x * 64;

    for (int idx = tid; idx < R * 64; idx += 128) {
        int s = idx >> 6, a = idx & 63;
        int ga = base + a;
        es[idx] = (ga < nAtoms) ? ei[s * nAtoms + ga] : 0;
    }
    __syncthreads();

    const int warp = tid >> 5, lane = tid & 31;
    for (int ri = warp; ri < R * 64; ri += 4) {
        int s = ri >> 6, a = ri & 63;
        const float* src = g_obj + (size_t)es[ri] * HID;
        Xs[(s * 64 + lane) * 66 + a]      = src[lane];
        Xs[(s * 64 + 32 + lane) * 66 + a] = src[32 + lane];
    }
    // Xs-write -> Xs-read ordering is provided by gemm_phase's barriers.

    const int cg = tid & 15;
    const int a0 = (tid >> 4) * 8;
    ull acc[NC * 4];

    gemm_phase<D, D>(W1, Xs, Ws, a0, cg, acc);

    #pragma unroll
    for (int c = 0; c < NC; c++) {
        int j = cg * NC + c;
        float bj = __ldg(b1 + j);
        #pragma unroll
        for (int p = 0; p < 4; p++) {
            float2 v = unpack2(acc[c * 4 + p]);
            v.x = fmaxf(v.x + bj, 0.f);
            v.y = fmaxf(v.y + bj, 0.f);
            *(float2*)(Xs + j * 66 + a0 + 2 * p) = v;
        }
    }

    gemm_phase<D, D>(W2, Xs, Ws, a0, cg, acc);

    #pragma unroll
    for (int c = 0; c < NC; c++) {
        int j = cg * NC + c;
        float bj = __ldg(b2 + j);
        int s = j >> 6, jj = j & 63;
        #pragma unroll
        for (int p = 0; p < 4; p++) {
            int a = a0 + 2 * p;
            float2 v = unpack2(acc[c * 4 + p]);
            if (base + a < nAtoms)
                atomicAdd(&g_agg[(size_t)es[s * 64 + a] * HID + jj], v.x + bj);
            if (base + a + 1 < nAtoms)
                atomicAdd(&g_agg[(size_t)es[s * 64 + a + 1] * HID + jj], v.y + bj);
        }
    }
}

// obj = mlp(cat([obj, agg])), in place. 64 objects per block.
__global__ void __launch_bounds__(128)
update_kernel(const float* __restrict__ Wu1, const float* __restrict__ bu1,
              const float* __restrict__ Wu2, const float* __restrict__ bu2,
              int nObj) {
    __shared__ float Xs[128 * 66];
    __shared__ float Ws[16 * 128];

    const int tid  = threadIdx.x;
    const int base = blockIdx.x * 64;
    const int warp = tid >> 5, lane = tid & 31;

    for (int a = warp; a < 64; a += 4) {
        int go = base + a;
        bool v = go < nObj;
        const float* po = g_obj + (size_t)go * HID;
        const float* pa = g_agg + (size_t)go * HID;
        Xs[lane * 66 + a]        = v ? po[lane]      : 0.f;
        Xs[(32 + lane) * 66 + a] = v ? po[32 + lane] : 0.f;
        Xs[(64 + lane) * 66 + a] = v ? pa[lane]      : 0.f;
        Xs[(96 + lane) * 66 + a] = v ? pa[32 + lane] : 0.f;
    }

    const int cg = tid & 15;
    const int a0 = (tid >> 4) * 8;
    ull acc[32];

    gemm_phase<128, 128>(Wu1, Xs, Ws, a0, cg, acc);

    #pragma unroll
    for (int c = 0; c < 8; c++) {
        int j = cg * 8 + c;
        float bj = __ldg(bu1 + j);
        #pragma unroll
        for (int p = 0; p < 4; p++) {
            float2 v = unpack2(acc[c * 4 + p]);
            v.x = fmaxf(v.x + bj, 0.f);
            v.y = fmaxf(v.y + bj, 0.f);
            *(float2*)(Xs + j * 66 + a0 + 2 * p) = v;
        }
    }

    gemm_phase<128, 64>(Wu2, Xs, Ws, a0, cg, acc);

    float b4[4];
    #pragma unroll
    for (int c = 0; c < 4; c++) b4[c] = __ldg(bu2 + cg * 4 + c);
    #pragma unroll
    for (int p = 0; p < 4; p++) {
        float2 v0 = unpack2(acc[0 * 4 + p]);
        float2 v1 = unpack2(acc[1 * 4 + p]);
        float2 v2 = unpack2(acc[2 * 4 + p]);
        float2 v3 = unpack2(acc[3 * 4 + p]);
        int go = base + a0 + 2 * p;
        if (go < nObj) {
            float4 o4 = make_float4(v0.x + b4[0], v1.x + b4[1], v2.x + b4[2], v3.x + b4[3]);
            *(float4*)(g_obj + (size_t)go * HID + cg * 4) = o4;
        }
        if (go + 1 < nObj) {
            float4 o4 = make_float4(v0.y + b4[0], v1.y + b4[1], v2.y + b4[2], v3.y + b4[3]);
            *(float4*)(g_obj + (size_t)(go + 1) * HID + cg * 4) = o4;
        }
    }
}

__global__ void zero_init_kernel(int nObj) {
    int i = blockIdx.x * 256 + threadIdx.x;
    if (i < nObj * HID)       g_obj[i] = 0.f;
    if (i < 6 * MAX_OBJ)      g_deg[i] = 0;
    if (i < MAX_GRAPHS * HID) g_pooled[i] = 0.f;
}

__global__ void zero_agg_kernel(int nObj) {
    int i = blockIdx.x * 256 + threadIdx.x;
    if (i < nObj * HID) g_agg[i] = 0.f;
}

// c_p = relu(b1) @ W2 + b2  (constant atom output while obj == 0)
__global__ void const_kernel(const float* b11, const float* w12, const float* b12,
                             const float* b21, const float* w22, const float* b22,
                             const float* b31, const float* w32, const float* b32) {
    int pred = blockIdx.x, j = threadIdx.x;
    const float *b1, *W2, *b2; int D, off;
    if (pred == 0)      { b1 = b11; W2 = w12; b2 = b12; D = 64;  off = 0;   }
    else if (pred == 1) { b1 = b21; W2 = w22; b2 = b22; D = 128; off = 64;  }
    else                { b1 = b31; W2 = w32; b2 = b32; D = 192; off = 192; }
    if (j < D) {
        float s = 0.f;
        for (int k = 0; k < D; k++) s = fmaf(fmaxf(b1[k], 0.f), W2[k * D + j], s);
        g_const[off + j] = s + b2[j];
    }
}

__global__ void deg_count_kernel(const int* __restrict__ ei, int n, int slotBase) {
    int s = blockIdx.y;
    int i = blockIdx.x * 256 + threadIdx.x;
    if (i < n) atomicAdd(&g_deg[(slotBase + s) * MAX_OBJ + ei[s * n + i]], 1);
}

__global__ void layer1_agg_kernel(int nObj) {
    int i = blockIdx.x * 256 + threadIdx.x;
    if (i >= nObj * HID) return;
    int o = i >> 6, c = i & 63;
    g_agg[i] = (float)g_deg[0 * MAX_OBJ + o] * g_const[c]
             + (float)g_deg[1 * MAX_OBJ + o] * g_const[64 + c]
             + (float)g_deg[2 * MAX_OBJ + o] * g_const[128 + c]
             + (float)g_deg[3 * MAX_OBJ + o] * g_const[192 + c]
             + (float)g_deg[4 * MAX_OBJ + o] * g_const[256 + c]
             + (float)g_deg[5 * MAX_OBJ + o] * g_const[320 + c];
}

// batch_obj is sorted: run-length accumulate per 64-object block, boundary atomics.
__global__ void pool_kernel(const int* __restrict__ batch, int nObj) {
    int c = threadIdx.x;            // 64 feature lanes
    int base = blockIdx.x * 64;
    int end = min(base + 64, nObj);
    int cur = -1; float s = 0.f;
    for (int o = base; o < end; o++) {
        int b = batch[o];
        if (b != cur) {
            if (cur >= 0) atomicAdd(&g_pooled[cur * HID + c], s);
            cur = b; s = 0.f;
        }
        s += g_obj[(size_t)o * HID + c];
    }
    if (cur >= 0) atomicAdd(&g_pooled[cur * HID + c], s);
}

__global__ void readout_kernel(const float* __restrict__ w1, const float* __restrict__ b1,
                               const float* __restrict__ w2, const float* __restrict__ b2,
                               float* __restrict__ out) {
    __shared__ float p[64];
    __shared__ float red[4];
    int g = blockIdx.x, t = threadIdx.x;   // 128 threads
    if (t < 64) p[t] = g_pooled[g * HID + t];
    __syncthreads();
    float acc = 0.f;
    #pragma unroll
    for (int k = 0; k < 64; k++) acc = fmaf(p[k], w1[k * 128 + t], acc);
    acc = fmaxf(acc + b1[t], 0.f) * w2[t];
    #pragma unroll
    for (int off = 16; off; off >>= 1) acc += __shfl_down_sync(0xffffffffu, acc, off);
    if ((t & 31) == 0) red[t >> 5] = acc;
    __syncthreads();
    if (t == 0) out[g] = red[0] + red[1] + red[2] + red[3] + b2[0];
}

extern "C" void kernel_launch(void* const* d_in, const int* in_sizes, int n_in,
                              void* d_out, int out_size) {
    const float* w_p1_1 = (const float*)d_in[4];
    const float* b_p1_1 = (const float*)d_in[5];
    const float* w_p1_2 = (const float*)d_in[6];
    const float* b_p1_2 = (const float*)d_in[7];
    const float* w_p2_1 = (const float*)d_in[8];
    const float* b_p2_1 = (const float*)d_in[9];
    const float* w_p2_2 = (const float*)d_in[10];
    const float* b_p2_2 = (const float*)d_in[11];
    const float* w_p3_1 = (const float*)d_in[12];
    const float* b_p3_1 = (const float*)d_in[13];
    const float* w_p3_2 = (const float*)d_in[14];
    const float* b_p3_2 = (const float*)d_in[15];
    const float* w_u1   = (const float*)d_in[16];
    const float* b_u1   = (const float*)d_in[17];
    const float* w_u2   = (const float*)d_in[18];
    const float* b_u2   = (const float*)d_in[19];
    const float* w_r1   = (const float*)d_in[20];
    const float* b_r1   = (const float*)d_in[21];
    const float* w_r2   = (const float*)d_in[22];
    const float* b_r2   = (const float*)d_in[23];
    const int*   ei_p1  = (const int*)d_in[24];
    const int*   ei_p2  = (const int*)d_in[25];
    const int*   ei_p3  = (const int*)d_in[26];
    const int*   batch  = (const int*)d_in[27];

    const int nObj = in_sizes[0];
    const int nP1  = in_sizes[24];
    const int nP2  = in_sizes[25] / 2;
    const int nP3  = in_sizes[26] / 3;
    const int nGraphs = out_size;
    float* out = (float*)d_out;

    const int smem1 = (64 * 66 + 16 * 64) * 4 + 64 * 4;
    const int smem2 = (128 * 66 + 16 * 128) * 4 + 128 * 4;
    const int smem3 = (192 * 66 + 16 * 192) * 4 + 192 * 4;
    cudaFuncSetAttribute(pred_kernel<3>, cudaFuncAttributeMaxDynamicSharedMemorySize, smem3);

    const int bObj = (nObj + 63) / 64;
    const int bP1  = (nP1 + 63) / 64;
    const int bP2  = (nP2 + 63) / 64;
    const int bP3  = (nP3 + 63) / 64;

    // init + layer-1 shortcut
    int zn = nObj * HID; if (6 * MAX_OBJ > zn) zn = 6 * MAX_OBJ;
    zero_init_kernel<<<(zn + 255) / 256, 256>>>(nObj);
    const_kernel<<<3, 192>>>(b_p1_1, w_p1_2, b_p1_2,
                             b_p2_1, w_p2_2, b_p2_2,
                             b_p3_1, w_p3_2, b_p3_2);
    deg_count_kernel<<<dim3((nP1 + 255) / 256, 1), 256>>>(ei_p1, nP1, 0);
    deg_count_kernel<<<dim3((nP2 + 255) / 256, 2), 256>>>(ei_p2, nP2, 1);
    deg_count_kernel<<<dim3((nP3 + 255) / 256, 3), 256>>>(ei_p3, nP3, 3);
    layer1_agg_kernel<<<(nObj * HID + 255) / 256, 256>>>(nObj);
    update_kernel<<<bObj, 128>>>(w_u1, b_u1, w_u2, b_u2, nObj);

    // layers 2..3
    for (int layer = 1; layer < 3; layer++) {
        zero_agg_kernel<<<(nObj * HID + 255) / 256, 256>>>(nObj);
        pred_kernel<1><<<bP1, 128, smem1>>>(ei_p1, nP1, w_p1_1, b_p1_1, w_p1_2, b_p1_2);
        pred_kernel<2><<<bP2, 128, smem2>>>(ei_p2, nP2, w_p2_1, b_p2_1, w_p2_2, b_p2_2);
        pred_kernel<3><<<bP3, 128, smem3>>>(ei_p3, nP3, w_p3_1, b_p3_1, w_p3_2, b_p3_2);
        update_kernel<<<bObj, 128>>>(w_u1, b_u1, w_u2, b_u2, nObj);
    }

    // pool + readout
    pool_kernel<<<bObj, 64>>>(batch, nObj);
    readout_kernel<<<nGraphs, 128>>>(w_r1, b_r1, w_r2, b_r2, out);
}

// round 5
// speedup vs baseline: 1.4450x; 1.4450x over previous
#include <cuda_runtime.h>
#include <cuda_bf16.h>

#define HID 64
#define MAX_OBJ 100000
#define MAX_GRAPHS 256

typedef unsigned int u32;
typedef unsigned long long u64;
typedef unsigned short u16;

__device__ float g_obj[MAX_OBJ * HID];
__device__ float g_agg[MAX_OBJ * HID];
__device__ int   g_deg[6 * MAX_OBJ];
__device__ float g_const[64 + 128 + 192];
__device__ float g_pooled[MAX_GRAPHS * HID];

// pre-transposed, bf16-split weights, layout [N][K+8] u16 per half.
// u16-element offsets:
//  p1: W1h 0      W1l 4608   W2h 9216   W2l 13824   (half = 64*72   = 4608)
//  p2: W1h 18432  W1l 35840  W2h 53248  W2l 70656   (half = 128*136 = 17408)
//  p3: W1h 88064  W1l 126464 W2h 164864 W2l 203264  (half = 192*200 = 38400)
//  u1: h 241664   l 259072                           (half = 128*136 = 17408)
//  u2: h 276480   l 285184                           (half = 64*136  = 8704)
__device__ __align__(16) u16 g_wbuf[293888];

// ---------------------------------------------------------------------------
// helpers
// ---------------------------------------------------------------------------
__device__ __forceinline__ u32 s2u(const void* p) {
    u32 a;
    asm("{ .reg .u64 t; cvta.to.shared.u64 t, %1; cvt.u32.u64 %0, t; }"
        : "=r"(a) : "l"(p));
    return a;
}
__device__ __forceinline__ u32 bpack(__nv_bfloat16 a, __nv_bfloat16 b) {
    __nv_bfloat162 t = __halves2bfloat162(a, b);
    return *reinterpret_cast<u32*>(&t);
}
__device__ __forceinline__ void split2(float x, float y, u32& h, u32& l) {
    __nv_bfloat16 hx = __float2bfloat16(x), hy = __float2bfloat16(y);
    __nv_bfloat16 lx = __float2bfloat16(x - __bfloat162float(hx));
    __nv_bfloat16 ly = __float2bfloat16(y - __bfloat162float(hy));
    h = bpack(hx, hy);
    l = bpack(lx, ly);
}

#define LDSM4(r, addr) \
    asm volatile("ldmatrix.sync.aligned.m8n8.x4.shared.b16 {%0,%1,%2,%3}, [%4];" \
        : "=r"((r)[0]), "=r"((r)[1]), "=r"((r)[2]), "=r"((r)[3]) : "r"(addr))
#define LDSM2(r, addr) \
    asm volatile("ldmatrix.sync.aligned.m8n8.x2.shared.b16 {%0,%1}, [%2];" \
        : "=r"((r)[0]), "=r"((r)[1]) : "r"(addr))
#define MMA16816(d, a, b) \
    asm volatile("mma.sync.aligned.m16n8k16.row.col.f32.bf16.bf16.f32 " \
        "{%0,%1,%2,%3}, {%4,%5,%6,%7}, {%8,%9}, {%0,%1,%2,%3};" \
        : "+f"((d)[0]), "+f"((d)[1]), "+f"((d)[2]), "+f"((d)[3]) \
        : "r"((a)[0]), "r"((a)[1]), "r"((a)[2]), "r"((a)[3]), \
          "r"((b)[0]), "r"((b)[1]))

__device__ __forceinline__ void red4(float* p, float a, float b, float c, float d) {
    asm volatile("red.global.add.v4.f32 [%0], {%1, %2, %3, %4};"
                 :: "l"(p), "f"(a), "f"(b), "f"(c), "f"(d) : "memory");
}

// ---------------------------------------------------------------------------
// warp GEMM: C[64, N] += X[64, K] @ Wt[N, K]^T, split-bf16 3-pass.
// X planes (hi/lo) at smem addrs xh/xl, layout [64][K+8] u16.
// Wt planes at wh/wl, layout [N][K+8] u16.
// warp w owns cols [w*N/4, (w+1)*N/4). acc = float[4][N/32][4].
// ---------------------------------------------------------------------------
template<int K, int N>
__device__ __forceinline__ void warp_gemm(u32 xh, u32 xl, u32 wh, u32 wl,
                                          int warp, int lane, float* acc) {
    constexpr int KP = K + 8;
    constexpr int NTW = N / 32;
    const u32 aoff = (u32)(((lane & 15) * KP + (lane >> 4) * 8) * 2);
    const u32 boff = (u32)((((warp * (N / 4)) + (lane & 7)) * KP + ((lane >> 3) & 1) * 8) * 2);
    #pragma unroll
    for (int kt = 0; kt < K / 16; kt++) {
        u32 A[2][4][4];
        #pragma unroll
        for (int mt = 0; mt < 4; mt++) {
            u32 o = aoff + (u32)((mt * 16 * KP + kt * 16) * 2);
            LDSM4(A[0][mt], xh + o);
            LDSM4(A[1][mt], xl + o);
        }
        #pragma unroll
        for (int nt = 0; nt < NTW; nt++) {
            u32 o = boff + (u32)((nt * 8 * KP + kt * 16) * 2);
            u32 Bh[2], Bl[2];
            LDSM2(Bh, wh + o);
            LDSM2(Bl, wl + o);
            #pragma unroll
            for (int mt = 0; mt < 4; mt++) {
                float* d = acc + (mt * NTW + nt) * 4;
                MMA16816(d, A[0][mt], Bh);
                MMA16816(d, A[0][mt], Bl);
                MMA16816(d, A[1][mt], Bh);
            }
        }
    }
}

// ---------------------------------------------------------------------------
// weight prep: W[K][N] f32 -> Wt[N][K+8] bf16 hi/lo
// one thread per OUTPUT element -> no write races (R4 bug fix)
// ---------------------------------------------------------------------------
__global__ void prep_weight_kernel(const float* __restrict__ W,
                                   u16* __restrict__ dh, u16* __restrict__ dl,
                                   int K, int N) {
    int i = blockIdx.x * 256 + threadIdx.x;
    int KP = K + 8;
    if (i >= N * KP) return;
    int n = i / KP, k = i - n * KP;
    u16 hv = 0, lv = 0;
    if (k < K) {
        float v = W[k * N + n];
        __nv_bfloat16 h = __float2bfloat16(v);
        __nv_bfloat16 l = __float2bfloat16(v - __bfloat162float(h));
        hv = *reinterpret_cast<u16*>(&h);
        lv = *reinterpret_cast<u16*>(&l);
    }
    dh[i] = hv;
    dl[i] = lv;
}

// ---------------------------------------------------------------------------
// fused predicate kernel: 64 atoms/block, 128 threads (4 warps)
// gather -> GEMM1 -> relu -> GEMM2 -> red.v4 scatter
// ---------------------------------------------------------------------------
template<int R>
__global__ void __launch_bounds__(128)
pred_mma_kernel(const int* __restrict__ ei, int nAtoms,
                const u16* __restrict__ W1h, const u16* __restrict__ W1l,
                const u16* __restrict__ W2h, const u16* __restrict__ W2l,
                const float* __restrict__ b1, const float* __restrict__ b2) {
    constexpr int D   = 64 * R;
    constexpr int KP  = D + 8;
    constexpr int NTW = D / 32;
    constexpr int WB  = D * KP * 2;    // bytes per weight half
    constexpr int XB  = 64 * KP * 2;   // bytes per X plane
    constexpr int FP  = D + 4;         // f32 out stride

    extern __shared__ char sm[];
    const u32 su = s2u(sm);
    const u32 WH = su, WL = su + WB, XHa = su + 2 * WB, XLa = XHa + XB;
    char* xh_c = sm + 2 * WB;
    char* xl_c = xh_c + XB;
    float* b1s = (float*)(sm + 2 * WB + 2 * XB);
    float* b2s = b1s + D;
    int*   es  = (int*)(b2s + D);
    float* F   = (float*)(sm + 2 * WB);   // overlays X planes after GEMM2

    const int tid = threadIdx.x, warp = tid >> 5, lane = tid & 31;
    const int base = blockIdx.x * 64;

    for (int i = tid; i < D; i += 128) { b1s[i] = b1[i]; b2s[i] = b2[i]; }
    for (int i = tid; i < R * 64; i += 128) {
        int a = i & 63, ga = base + a;
        es[i] = (ga < nAtoms) ? ei[(i >> 6) * nAtoms + ga] : 0;
    }
    {   // stage W1 (prepped layout -> linear copy)
        const uint4* s1 = (const uint4*)W1h; const uint4* s2 = (const uint4*)W1l;
        uint4* d1 = (uint4*)sm; uint4* d2 = (uint4*)(sm + WB);
        for (int i = tid; i < WB / 16; i += 128) { d1[i] = s1[i]; d2[i] = s2[i]; }
    }
    __syncthreads();

    {   // gather X rows: thread pair per atom
        int a = tid >> 1, h = tid & 1;
        #pragma unroll
        for (int s = 0; s < R; s++) {
            const float* src = g_obj + (size_t)es[s * 64 + a] * HID + h * 32;
            #pragma unroll
            for (int q = 0; q < 8; q++) {
                float4 v = *(const float4*)(src + q * 4);
                u32 h0, l0, h1, l1;
                split2(v.x, v.y, h0, l0);
                split2(v.z, v.w, h1, l1);
                u32 bo = (u32)(a * KP + s * 64 + h * 32 + q * 4) * 2;
                *(u64*)(xh_c + bo) = (u64)h0 | ((u64)h1 << 32);
                *(u64*)(xl_c + bo) = (u64)l0 | ((u64)l1 << 32);
            }
        }
    }
    __syncthreads();

    float acc[4 * NTW * 4];
    #pragma unroll
    for (int i = 0; i < 4 * NTW * 4; i++) acc[i] = 0.f;
    warp_gemm<D, D>(XHa, XLa, WH, WL, warp, lane, acc);
    __syncthreads();

    // epilogue1: H = relu(C + b1) -> X planes; stage W2
    #pragma unroll
    for (int mt = 0; mt < 4; mt++)
        #pragma unroll
        for (int nt = 0; nt < NTW; nt++) {
            float* d = acc + (mt * NTW + nt) * 4;
            int row = mt * 16 + (lane >> 2);
            int col = warp * (D / 4) + nt * 8 + 2 * (lane & 3);
            u32 hh, ll;
            float x0 = fmaxf(d[0] + b1s[col], 0.f), x1 = fmaxf(d[1] + b1s[col + 1], 0.f);
            split2(x0, x1, hh, ll);
            *(u32*)(xh_c + (row * KP + col) * 2) = hh;
            *(u32*)(xl_c + (row * KP + col) * 2) = ll;
            float x2 = fmaxf(d[2] + b1s[col], 0.f), x3 = fmaxf(d[3] + b1s[col + 1], 0.f);
            split2(x2, x3, hh, ll);
            *(u32*)(xh_c + ((row + 8) * KP + col) * 2) = hh;
            *(u32*)(xl_c + ((row + 8) * KP + col) * 2) = ll;
        }
    {
        const uint4* s1 = (const uint4*)W2h; const uint4* s2 = (const uint4*)W2l;
        uint4* d1 = (uint4*)sm; uint4* d2 = (uint4*)(sm + WB);
        for (int i = tid; i < WB / 16; i += 128) { d1[i] = s1[i]; d2[i] = s2[i]; }
    }
    __syncthreads();

    #pragma unroll
    for (int i = 0; i < 4 * NTW * 4; i++) acc[i] = 0.f;
    warp_gemm<D, D>(XHa, XLa, WH, WL, warp, lane, acc);
    __syncthreads();

    // epilogue2: C + b2 -> F (f32, stride FP)
    #pragma unroll
    for (int mt = 0; mt < 4; mt++)
        #pragma unroll
        for (int nt = 0; nt < NTW; nt++) {
            float* d = acc + (mt * NTW + nt) * 4;
            int row = mt * 16 + (lane >> 2);
            int col = warp * (D / 4) + nt * 8 + 2 * (lane & 3);
            *(float2*)(F + row * FP + col) =
                make_float2(d[0] + b2s[col], d[1] + b2s[col + 1]);
            *(float2*)(F + (row + 8) * FP + col) =
                make_float2(d[2] + b2s[col], d[3] + b2s[col + 1]);
        }
    __syncthreads();

    // scatter: vector reductions into g_agg
    {
        int a = tid & 63, hf = tid >> 6;
        if (base + a < nAtoms) {
            #pragma unroll
            for (int j = hf * (D / 2); j < hf * (D / 2) + D / 2; j += 4) {
                float* dst = g_agg + (size_t)es[(j >> 6) * 64 + a] * HID + (j & 63);
                const float* f = F + a * FP + j;
                red4(dst, f[0], f[1], f[2], f[3]);
            }
        }
    }
}

// ---------------------------------------------------------------------------
// object update: obj = mlp(cat([obj, agg])), 64 objects/block
// ---------------------------------------------------------------------------
__global__ void __launch_bounds__(128)
update_mma_kernel(const u16* __restrict__ U1h, const u16* __restrict__ U1l,
                  const u16* __restrict__ U2h, const u16* __restrict__ U2l,
                  const float* __restrict__ bu1, const float* __restrict__ bu2,
                  int nObj) {
    constexpr int K = 128, KP = 136;
    constexpr int WB = 128 * KP * 2;   // U1 half bytes (U2 smaller, same region)
    constexpr int XB = 64 * KP * 2;

    extern __shared__ char sm[];
    const u32 su = s2u(sm);
    const u32 WH = su, WL = su + WB, XHa = su + 2 * WB, XLa = XHa + XB;
    char* xh_c = sm + 2 * WB;
    char* xl_c = xh_c + XB;
    float* b1s = (float*)(sm + 2 * WB + 2 * XB);
    float* b2s = b1s + 128;
    float* F   = (float*)(sm + 2 * WB);
    constexpr int FP = 68;

    const int tid = threadIdx.x, warp = tid >> 5, lane = tid & 31;
    const int base = blockIdx.x * 64;

    for (int i = tid; i < 128; i += 128) b1s[i] = bu1[i];
    if (tid < 64) b2s[tid] = bu2[tid];
    {
        const uint4* s1 = (const uint4*)U1h; const uint4* s2 = (const uint4*)U1l;
        uint4* d1 = (uint4*)sm; uint4* d2 = (uint4*)(sm + WB);
        for (int i = tid; i < WB / 16; i += 128) { d1[i] = s1[i]; d2[i] = s2[i]; }
    }

    {   // gather cat(obj, agg)
        int a = tid >> 1, h = tid & 1;
        int go = base + a;
        int gc = (go < nObj) ? go : 0;
        const float* src = (h ? g_agg : g_obj) + (size_t)gc * HID;
        #pragma unroll
        for (int q = 0; q < 16; q++) {
            float4 v = *(const float4*)(src + q * 4);
            u32 h0, l0, h1, l1;
            split2(v.x, v.y, h0, l0);
            split2(v.z, v.w, h1, l1);
            u32 bo = (u32)(a * KP + h * 64 + q * 4) * 2;
            *(u64*)(xh_c + bo) = (u64)h0 | ((u64)h1 << 32);
            *(u64*)(xl_c + bo) = (u64)l0 | ((u64)l1 << 32);
        }
    }
    __syncthreads();

    float acc[4 * 4 * 4];
    #pragma unroll
    for (int i = 0; i < 64; i++) acc[i] = 0.f;
    warp_gemm<128, 128>(XHa, XLa, WH, WL, warp, lane, acc);
    __syncthreads();

    // epilogue1 -> H in X planes; stage U2
    #pragma unroll
    for (int mt = 0; mt < 4; mt++)
        #pragma unroll
        for (int nt = 0; nt < 4; nt++) {
            float* d = acc + (mt * 4 + nt) * 4;
            int row = mt * 16 + (lane >> 2);
            int col = warp * 32 + nt * 8 + 2 * (lane & 3);
            u32 hh, ll;
            float x0 = fmaxf(d[0] + b1s[col], 0.f), x1 = fmaxf(d[1] + b1s[col + 1], 0.f);
            split2(x0, x1, hh, ll);
            *(u32*)(xh_c + (row * KP + col) * 2) = hh;
            *(u32*)(xl_c + (row * KP + col) * 2) = ll;
            float x2 = fmaxf(d[2] + b1s[col], 0.f), x3 = fmaxf(d[3] + b1s[col + 1], 0.f);
            split2(x2, x3, hh, ll);
            *(u32*)(xh_c + ((row + 8) * KP + col) * 2) = hh;
            *(u32*)(xl_c + ((row + 8) * KP + col) * 2) = ll;
        }
    {
        constexpr int WB2 = 64 * KP * 2;
        const uint4* s1 = (const uint4*)U2h; const uint4* s2 = (const uint4*)U2l;
        uint4* d1 = (uint4*)sm; uint4* d2 = (uint4*)(sm + WB);
        for (int i = tid; i < WB2 / 16; i += 128) { d1[i] = s1[i]; d2[i] = s2[i]; }
    }
    __syncthreads();

    #pragma unroll
    for (int i = 0; i < 32; i++) acc[i] = 0.f;
    warp_gemm<128, 64>(XHa, XLa, WH, WL, warp, lane, acc);
    __syncthreads();

    // epilogue2 -> F (f32 [64][68])
    #pragma unroll
    for (int mt = 0; mt < 4; mt++)
        #pragma unroll
        for (int nt = 0; nt < 2; nt++) {
            float* d = acc + (mt * 2 + nt) * 4;
            int row = mt * 16 + (lane >> 2);
            int col = warp * 16 + nt * 8 + 2 * (lane & 3);
            *(float2*)(F + row * FP + col) =
                make_float2(d[0] + b2s[col], d[1] + b2s[col + 1]);
            *(float2*)(F + (row + 8) * FP + col) =
                make_float2(d[2] + b2s[col], d[3] + b2s[col + 1]);
        }
    __syncthreads();

    {   // write back obj rows
        int a = tid >> 1, h = tid & 1;
        int go = base + a;
        if (go < nObj) {
            float* dst = g_obj + (size_t)go * HID + h * 32;
            const float* f = F + a * FP + h * 32;
            #pragma unroll
            for (int q = 0; q < 8; q++)
                *(float4*)(dst + q * 4) = *(const float4*)(f + q * 4);
        }
    }
}

// ---------------------------------------------------------------------------
// layer-1 shortcut + small kernels (validated in R1 baseline)
// ---------------------------------------------------------------------------
__global__ void zero_init_kernel(int nObj) {
    int i = blockIdx.x * 256 + threadIdx.x;
    if (i < nObj * HID)       g_obj[i] = 0.f;
    if (i < 6 * MAX_OBJ)      g_deg[i] = 0;
    if (i < MAX_GRAPHS * HID) g_pooled[i] = 0.f;
}
__global__ void zero_agg_kernel(int nObj) {
    int i = blockIdx.x * 256 + threadIdx.x;
    if (i < nObj * HID) g_agg[i] = 0.f;
}
__global__ void const_kernel(const float* b11, const float* w12, const float* b12,
                             const float* b21, const float* w22, const float* b22,
                             const float* b31, const float* w32, const float* b32) {
    int pred = blockIdx.x, j = threadIdx.x;
    const float *b1, *W2, *b2; int D, off;
    if (pred == 0)      { b1 = b11; W2 = w12; b2 = b12; D = 64;  off = 0;   }
    else if (pred == 1) { b1 = b21; W2 = w22; b2 = b22; D = 128; off = 64;  }
    else                { b1 = b31; W2 = w32; b2 = b32; D = 192; off = 192; }
    if (j < D) {
        float s = 0.f;
        for (int k = 0; k < D; k++) s = fmaf(fmaxf(b1[k], 0.f), W2[k * D + j], s);
        g_const[off + j] = s + b2[j];
    }
}
__global__ void deg_count_kernel(const int* __restrict__ ei, int n, int slotBase) {
    int s = blockIdx.y;
    int i = blockIdx.x * 256 + threadIdx.x;
    if (i < n) atomicAdd(&g_deg[(slotBase + s) * MAX_OBJ + ei[s * n + i]], 1);
}
__global__ void layer1_agg_kernel(int nObj) {
    int i = blockIdx.x * 256 + threadIdx.x;
    if (i >= nObj * HID) return;
    int o = i >> 6, c = i & 63;
    g_agg[i] = (float)g_deg[0 * MAX_OBJ + o] * g_const[c]
             + (float)g_deg[1 * MAX_OBJ + o] * g_const[64 + c]
             + (float)g_deg[2 * MAX_OBJ + o] * g_const[128 + c]
             + (float)g_deg[3 * MAX_OBJ + o] * g_const[192 + c]
             + (float)g_deg[4 * MAX_OBJ + o] * g_const[256 + c]
             + (float)g_deg[5 * MAX_OBJ + o] * g_const[320 + c];
}
__global__ void pool_kernel(const int* __restrict__ batch, int nObj) {
    int c = threadIdx.x;
    int base = blockIdx.x * 64;
    int end = min(base + 64, nObj);
    int cur = -1; float s = 0.f;
    for (int o = base; o < end; o++) {
        int b = batch[o];
        if (b != cur) {
            if (cur >= 0) atomicAdd(&g_pooled[cur * HID + c], s);
            cur = b; s = 0.f;
        }
        s += g_obj[(size_t)o * HID + c];
    }
    if (cur >= 0) atomicAdd(&g_pooled[cur * HID + c], s);
}
__global__ void readout_kernel(const float* __restrict__ w1, const float* __restrict__ b1,
                               const float* __restrict__ w2, const float* __restrict__ b2,
                               float* __restrict__ out) {
    __shared__ float p[64];
    __shared__ float red[4];
    int g = blockIdx.x, t = threadIdx.x;
    if (t < 64) p[t] = g_pooled[g * HID + t];
    __syncthreads();
    float acc = 0.f;
    #pragma unroll
    for (int k = 0; k < 64; k++) acc = fmaf(p[k], w1[k * 128 + t], acc);
    acc = fmaxf(acc + b1[t], 0.f) * w2[t];
    #pragma unroll
    for (int off = 16; off; off >>= 1) acc += __shfl_down_sync(0xffffffffu, acc, off);
    if ((t & 31) == 0) red[t >> 5] = acc;
    __syncthreads();
    if (t == 0) out[g] = red[0] + red[1] + red[2] + red[3] + b2[0];
}

// ---------------------------------------------------------------------------
extern "C" void kernel_launch(void* const* d_in, const int* in_sizes, int n_in,
                              void* d_out, int out_size) {
    const float* w_p1_1 = (const float*)d_in[4];
    const float* b_p1_1 = (const float*)d_in[5];
    const float* w_p1_2 = (const float*)d_in[6];
    const float* b_p1_2 = (const float*)d_in[7];
    const float* w_p2_1 = (const float*)d_in[8];
    const float* b_p2_1 = (const float*)d_in[9];
    const float* w_p2_2 = (const float*)d_in[10];
    const float* b_p2_2 = (const float*)d_in[11];
    const float* w_p3_1 = (const float*)d_in[12];
    const float* b_p3_1 = (const float*)d_in[13];
    const float* w_p3_2 = (const float*)d_in[14];
    const float* b_p3_2 = (const float*)d_in[15];
    const float* w_u1   = (const float*)d_in[16];
    const float* b_u1   = (const float*)d_in[17];
    const float* w_u2   = (const float*)d_in[18];
    const float* b_u2   = (const float*)d_in[19];
    const float* w_r1   = (const float*)d_in[20];
    const float* b_r1   = (const float*)d_in[21];
    const float* w_r2   = (const float*)d_in[22];
    const float* b_r2   = (const float*)d_in[23];
    const int*   ei_p1  = (const int*)d_in[24];
    const int*   ei_p2  = (const int*)d_in[25];
    const int*   ei_p3  = (const int*)d_in[26];
    const int*   batch  = (const int*)d_in[27];

    const int nObj = in_sizes[0];
    const int nP1  = in_sizes[24];
    const int nP2  = in_sizes[25] / 2;
    const int nP3  = in_sizes[26] / 3;
    const int nGraphs = out_size;
    float* out = (float*)d_out;

    u16* wb = nullptr;
    cudaGetSymbolAddress((void**)&wb, g_wbuf);

    // dynamic smem: 2*WB + 2*XB + biases + es
    const int smem1 = 2 * (64 * 72 * 2)   + 2 * (64 * 72 * 2)   + 8 * 64  + 1 * 64 * 4;
    const int smem2 = 2 * (128 * 136 * 2) + 2 * (64 * 136 * 2)  + 8 * 128 + 2 * 64 * 4;
    const int smem3 = 2 * (192 * 200 * 2) + 2 * (64 * 200 * 2)  + 8 * 192 + 3 * 64 * 4;
    const int smemU = 2 * (128 * 136 * 2) + 2 * (64 * 136 * 2)  + 128 * 4 + 64 * 4;
    cudaFuncSetAttribute(pred_mma_kernel<1>, cudaFuncAttributeMaxDynamicSharedMemorySize, smem1);
    cudaFuncSetAttribute(pred_mma_kernel<2>, cudaFuncAttributeMaxDynamicSharedMemorySize, smem2);
    cudaFuncSetAttribute(pred_mma_kernel<3>, cudaFuncAttributeMaxDynamicSharedMemorySize, smem3);
    cudaFuncSetAttribute(update_mma_kernel, cudaFuncAttributeMaxDynamicSharedMemorySize, smemU);

    // weight prep: Wt[N][K+8] bf16 hi/lo (one thread per output element)
    prep_weight_kernel<<<(64 * 72 + 255) / 256, 256>>>(w_p1_1, wb + 0,      wb + 4608,   64, 64);
    prep_weight_kernel<<<(64 * 72 + 255) / 256, 256>>>(w_p1_2, wb + 9216,   wb + 13824,  64, 64);
    prep_weight_kernel<<<(128 * 136 + 255) / 256, 256>>>(w_p2_1, wb + 18432, wb + 35840, 128, 128);
    prep_weight_kernel<<<(128 * 136 + 255) / 256, 256>>>(w_p2_2, wb + 53248, wb + 70656, 128, 128);
    prep_weight_kernel<<<(192 * 200 + 255) / 256, 256>>>(w_p3_1, wb + 88064, wb + 126464, 192, 192);
    prep_weight_kernel<<<(192 * 200 + 255) / 256, 256>>>(w_p3_2, wb + 164864, wb + 203264, 192, 192);
    prep_weight_kernel<<<(128 * 136 + 255) / 256, 256>>>(w_u1, wb + 241664, wb + 259072, 128, 128);
    prep_weight_kernel<<<(64 * 136 + 255) / 256, 256>>>(w_u2, wb + 276480, wb + 285184, 128, 64);

    const int bObj = (nObj + 63) / 64;
    const int bP1  = (nP1 + 63) / 64;
    const int bP2  = (nP2 + 63) / 64;
    const int bP3  = (nP3 + 63) / 64;

    // init + layer-1 shortcut
    int zn = nObj * HID; if (6 * MAX_OBJ > zn) zn = 6 * MAX_OBJ;
    zero_init_kernel<<<(zn + 255) / 256, 256>>>(nObj);
    const_kernel<<<3, 192>>>(b_p1_1, w_p1_2, b_p1_2,
                             b_p2_1, w_p2_2, b_p2_2,
                             b_p3_1, w_p3_2, b_p3_2);
    deg_count_kernel<<<dim3((nP1 + 255) / 256, 1), 256>>>(ei_p1, nP1, 0);
    deg_count_kernel<<<dim3((nP2 + 255) / 256, 2), 256>>>(ei_p2, nP2, 1);
    deg_count_kernel<<<dim3((nP3 + 255) / 256, 3), 256>>>(ei_p3, nP3, 3);
    layer1_agg_kernel<<<(nObj * HID + 255) / 256, 256>>>(nObj);
    update_mma_kernel<<<bObj, 128, smemU>>>(wb + 241664, wb + 259072,
                                            wb + 276480, wb + 285184, b_u1, b_u2, nObj);

    // layers 2..3
    for (int layer = 1; layer < 3; layer++) {
        zero_agg_kernel<<<(nObj * HID + 255) / 256, 256>>>(nObj);
        pred_mma_kernel<1><<<bP1, 128, smem1>>>(ei_p1, nP1, wb + 0, wb + 4608,
                                                wb + 9216, wb + 13824, b_p1_1, b_p1_2);
        pred_mma_kernel<2><<<bP2, 128, smem2>>>(ei_p2, nP2, wb + 18432, wb + 35840,
                                                wb + 53248, wb + 70656, b_p2_1, b_p2_2);
        pred_mma_kernel<3><<<bP3, 128, smem3>>>(ei_p3, nP3, wb + 88064, wb + 126464,
                                                wb + 164864, wb + 203264, b_p3_1, b_p3_2);
        update_mma_kernel<<<bObj, 128, smemU>>>(wb + 241664, wb + 259072,
                                                wb + 276480, wb + 285184, b_u1, b_u2, nObj);
    }

    // pool + readout
    pool_kernel<<<bObj, 64>>>(batch, nObj);
    readout_kernel<<<nGraphs, 128>>>(w_r1, b_r1, w_r2, b_r2, out);
}

// round 6
// speedup vs baseline: 1.6555x; 1.1457x over previous
#include <cuda_runtime.h>
#include <cuda_bf16.h>

#define HID 64
#define MAX_OBJ 100000
#define MAX_GRAPHS 256

typedef unsigned int u32;
typedef unsigned long long u64;
typedef unsigned short u16;

__device__ float g_obj[MAX_OBJ * HID];
__device__ float g_agg[MAX_OBJ * HID];
__device__ int   g_deg[6 * MAX_OBJ];
__device__ float g_const[64 + 128 + 192];
__device__ float g_pooled[MAX_GRAPHS * HID];

// pre-transposed, bf16-split weights, layout [N][K+8] u16 per half.
__device__ __align__(16) u16 g_wbuf[293888];

// ---------------------------------------------------------------------------
// helpers
// ---------------------------------------------------------------------------
__device__ __forceinline__ u32 s2u(const void* p) {
    u32 a;
    asm("{ .reg .u64 t; cvta.to.shared.u64 t, %1; cvt.u32.u64 %0, t; }"
        : "=r"(a) : "l"(p));
    return a;
}
__device__ __forceinline__ u32 bpack(__nv_bfloat16 a, __nv_bfloat16 b) {
    __nv_bfloat162 t = __halves2bfloat162(a, b);
    return *reinterpret_cast<u32*>(&t);
}
__device__ __forceinline__ void split2(float x, float y, u32& h, u32& l) {
    __nv_bfloat16 hx = __float2bfloat16(x), hy = __float2bfloat16(y);
    __nv_bfloat16 lx = __float2bfloat16(x - __bfloat162float(hx));
    __nv_bfloat16 ly = __float2bfloat16(y - __bfloat162float(hy));
    h = bpack(hx, hy);
    l = bpack(lx, ly);
}

#define LDSM4(r, addr) \
    asm volatile("ldmatrix.sync.aligned.m8n8.x4.shared.b16 {%0,%1,%2,%3}, [%4];" \
        : "=r"((r)[0]), "=r"((r)[1]), "=r"((r)[2]), "=r"((r)[3]) : "r"(addr))
#define LDSM2(r, addr) \
    asm volatile("ldmatrix.sync.aligned.m8n8.x2.shared.b16 {%0,%1}, [%2];" \
        : "=r"((r)[0]), "=r"((r)[1]) : "r"(addr))
#define MMA16816(d, a, b) \
    asm volatile("mma.sync.aligned.m16n8k16.row.col.f32.bf16.bf16.f32 " \
        "{%0,%1,%2,%3}, {%4,%5,%6,%7}, {%8,%9}, {%0,%1,%2,%3};" \
        : "+f"((d)[0]), "+f"((d)[1]), "+f"((d)[2]), "+f"((d)[3]) \
        : "r"((a)[0]), "r"((a)[1]), "r"((a)[2]), "r"((a)[3]), \
          "r"((b)[0]), "r"((b)[1]))

__device__ __forceinline__ void red4(float* p, float a, float b, float c, float d) {
    asm volatile("red.global.add.v4.f32 [%0], {%1, %2, %3, %4};"
                 :: "l"(p), "f"(a), "f"(b), "f"(c), "f"(d) : "memory");
}

// ---------------------------------------------------------------------------
// warp GEMM over NWARP warps in N: C[64, N] += X[64, K] @ Wt[N, K]^T,
// split-bf16 3-pass. X planes at xh/xl ([64][K+8] u16), Wt at wh/wl
// ([N][K+8] u16). warp w owns cols [w*N/NWARP, (w+1)*N/NWARP).
// acc = float[4][NTW][4], NTW = N/(8*NWARP).
// ---------------------------------------------------------------------------
template<int K, int N, int NWARP>
__device__ __forceinline__ void warp_gemm(u32 xh, u32 xl, u32 wh, u32 wl,
                                          int warp, int lane, float* acc) {
    constexpr int KP  = K + 8;
    constexpr int NPW = N / NWARP;
    constexpr int NTW = NPW / 8;
    const u32 aoff = (u32)(((lane & 15) * KP + (lane >> 4) * 8) * 2);
    const u32 boff = (u32)((((warp * NPW) + (lane & 7)) * KP + ((lane >> 3) & 1) * 8) * 2);
    #pragma unroll
    for (int kt = 0; kt < K / 16; kt++) {
        u32 A[2][4][4];
        #pragma unroll
        for (int mt = 0; mt < 4; mt++) {
            u32 o = aoff + (u32)((mt * 16 * KP + kt * 16) * 2);
            LDSM4(A[0][mt], xh + o);
            LDSM4(A[1][mt], xl + o);
        }
        #pragma unroll
        for (int nt = 0; nt < NTW; nt++) {
            u32 o = boff + (u32)((nt * 8 * KP + kt * 16) * 2);
            u32 Bh[2], Bl[2];
            LDSM2(Bh, wh + o);
            LDSM2(Bl, wl + o);
            #pragma unroll
            for (int mt = 0; mt < 4; mt++) {
                float* d = acc + (mt * NTW + nt) * 4;
                MMA16816(d, A[0][mt], Bh);
                MMA16816(d, A[0][mt], Bl);
                MMA16816(d, A[1][mt], Bh);
            }
        }
    }
}

// ---------------------------------------------------------------------------
// weight prep: W[K][N] f32 -> Wt[N][K+8] bf16 hi/lo (one thread per output)
// ---------------------------------------------------------------------------
__global__ void prep_weight_kernel(const float* __restrict__ W,
                                   u16* __restrict__ dh, u16* __restrict__ dl,
                                   int K, int N) {
    int i = blockIdx.x * 256 + threadIdx.x;
    int KP = K + 8;
    if (i >= N * KP) return;
    int n = i / KP, k = i - n * KP;
    u16 hv = 0, lv = 0;
    if (k < K) {
        float v = W[k * N + n];
        __nv_bfloat16 h = __float2bfloat16(v);
        __nv_bfloat16 l = __float2bfloat16(v - __bfloat162float(h));
        hv = *reinterpret_cast<u16*>(&h);
        lv = *reinterpret_cast<u16*>(&l);
    }
    dh[i] = hv;
    dl[i] = lv;
}

// ---------------------------------------------------------------------------
// fused predicate kernel: 64 atoms/block, 256 threads (8 warps, N-split)
// gather -> GEMM1 -> relu -> GEMM2 -> red.v4 scatter
// ---------------------------------------------------------------------------
template<int R>
__global__ void __launch_bounds__(256)
pred_mma_kernel(const int* __restrict__ ei, int nAtoms,
                const u16* __restrict__ W1h, const u16* __restrict__ W1l,
                const u16* __restrict__ W2h, const u16* __restrict__ W2l,
                const float* __restrict__ b1, const float* __restrict__ b2) {
    constexpr int D   = 64 * R;
    constexpr int KP  = D + 8;
    constexpr int NTW = D / 64;        // tiles per warp (8 warps)
    constexpr int WB  = D * KP * 2;    // bytes per weight half
    constexpr int XB  = 64 * KP * 2;   // bytes per X plane
    constexpr int FP  = D + 4;         // f32 out stride

    extern __shared__ char sm[];
    const u32 su = s2u(sm);
    const u32 WH = su, WL = su + WB, XHa = su + 2 * WB, XLa = XHa + XB;
    char* xh_c = sm + 2 * WB;
    char* xl_c = xh_c + XB;
    float* b1s = (float*)(sm + 2 * WB + 2 * XB);
    float* b2s = b1s + D;
    int*   es  = (int*)(b2s + D);
    float* F   = (float*)(sm + 2 * WB);   // overlays X planes after GEMM2

    const int tid = threadIdx.x, warp = tid >> 5, lane = tid & 31;
    const int base = blockIdx.x * 64;

    for (int i = tid; i < D; i += 256) { b1s[i] = b1[i]; b2s[i] = b2[i]; }
    if (tid < R * 64) {
        int a = tid & 63, ga = base + a;
        es[tid] = (ga < nAtoms) ? ei[(tid >> 6) * nAtoms + ga] : 0;
    }
    {   // stage W1
        const uint4* s1 = (const uint4*)W1h; const uint4* s2 = (const uint4*)W1l;
        uint4* d1 = (uint4*)sm; uint4* d2 = (uint4*)(sm + WB);
        for (int i = tid; i < WB / 16; i += 256) { d1[i] = s1[i]; d2[i] = s2[i]; }
    }
    __syncthreads();

    {   // gather X rows: thread quad per atom
        int a = tid >> 2, h = tid & 3;
        #pragma unroll
        for (int s = 0; s < R; s++) {
            const float* src = g_obj + (size_t)es[s * 64 + a] * HID + h * 16;
            #pragma unroll
            for (int q = 0; q < 4; q++) {
                float4 v = *(const float4*)(src + q * 4);
                u32 h0, l0, h1, l1;
                split2(v.x, v.y, h0, l0);
                split2(v.z, v.w, h1, l1);
                u32 bo = (u32)(a * KP + s * 64 + h * 16 + q * 4) * 2;
                *(u64*)(xh_c + bo) = (u64)h0 | ((u64)h1 << 32);
                *(u64*)(xl_c + bo) = (u64)l0 | ((u64)l1 << 32);
            }
        }
    }
    __syncthreads();

    float acc[4 * NTW * 4];
    #pragma unroll
    for (int i = 0; i < 4 * NTW * 4; i++) acc[i] = 0.f;
    warp_gemm<D, D, 8>(XHa, XLa, WH, WL, warp, lane, acc);
    __syncthreads();

    // epilogue1: H = relu(C + b1) -> X planes; stage W2
    #pragma unroll
    for (int mt = 0; mt < 4; mt++)
        #pragma unroll
        for (int nt = 0; nt < NTW; nt++) {
            float* d = acc + (mt * NTW + nt) * 4;
            int row = mt * 16 + (lane >> 2);
            int col = warp * (D / 8) + nt * 8 + 2 * (lane & 3);
            u32 hh, ll;
            float x0 = fmaxf(d[0] + b1s[col], 0.f), x1 = fmaxf(d[1] + b1s[col + 1], 0.f);
            split2(x0, x1, hh, ll);
            *(u32*)(xh_c + (row * KP + col) * 2) = hh;
            *(u32*)(xl_c + (row * KP + col) * 2) = ll;
            float x2 = fmaxf(d[2] + b1s[col], 0.f), x3 = fmaxf(d[3] + b1s[col + 1], 0.f);
            split2(x2, x3, hh, ll);
            *(u32*)(xh_c + ((row + 8) * KP + col) * 2) = hh;
            *(u32*)(xl_c + ((row + 8) * KP + col) * 2) = ll;
        }
    {
        const uint4* s1 = (const uint4*)W2h; const uint4* s2 = (const uint4*)W2l;
        uint4* d1 = (uint4*)sm; uint4* d2 = (uint4*)(sm + WB);
        for (int i = tid; i < WB / 16; i += 256) { d1[i] = s1[i]; d2[i] = s2[i]; }
    }
    __syncthreads();

    #pragma unroll
    for (int i = 0; i < 4 * NTW * 4; i++) acc[i] = 0.f;
    warp_gemm<D, D, 8>(XHa, XLa, WH, WL, warp, lane, acc);
    __syncthreads();

    // epilogue2: C + b2 -> F (f32, stride FP)
    #pragma unroll
    for (int mt = 0; mt < 4; mt++)
        #pragma unroll
        for (int nt = 0; nt < NTW; nt++) {
            float* d = acc + (mt * NTW + nt) * 4;
            int row = mt * 16 + (lane >> 2);
            int col = warp * (D / 8) + nt * 8 + 2 * (lane & 3);
            *(float2*)(F + row * FP + col) =
                make_float2(d[0] + b2s[col], d[1] + b2s[col + 1]);
            *(float2*)(F + (row + 8) * FP + col) =
                make_float2(d[2] + b2s[col], d[3] + b2s[col + 1]);
        }
    __syncthreads();

    // scatter: vector reductions into g_agg (each thread: 1/4 of cols)
    {
        int a = tid & 63, qf = tid >> 6;
        if (base + a < nAtoms) {
            #pragma unroll
            for (int j = qf * (D / 4); j < qf * (D / 4) + D / 4; j += 4) {
                float* dst = g_agg + (size_t)es[(j >> 6) * 64 + a] * HID + (j & 63);
                const float* f = F + a * FP + j;
                red4(dst, f[0], f[1], f[2], f[3]);
            }
        }
    }
}

// ---------------------------------------------------------------------------
// object update: obj = mlp(cat([obj, agg])), 64 objects/block, 256 threads
// ---------------------------------------------------------------------------
__global__ void __launch_bounds__(256)
update_mma_kernel(const u16* __restrict__ U1h, const u16* __restrict__ U1l,
                  const u16* __restrict__ U2h, const u16* __restrict__ U2l,
                  const float* __restrict__ bu1, const float* __restrict__ bu2,
                  int nObj) {
    constexpr int KP = 136;
    constexpr int WB = 128 * KP * 2;
    constexpr int XB = 64 * KP * 2;
    constexpr int FP = 68;

    extern __shared__ char sm[];
    const u32 su = s2u(sm);
    const u32 WH = su, WL = su + WB, XHa = su + 2 * WB, XLa = XHa + XB;
    char* xh_c = sm + 2 * WB;
    char* xl_c = xh_c + XB;
    float* b1s = (float*)(sm + 2 * WB + 2 * XB);
    float* b2s = b1s + 128;
    float* F   = (float*)(sm + 2 * WB);

    const int tid = threadIdx.x, warp = tid >> 5, lane = tid & 31;
    const int base = blockIdx.x * 64;

    if (tid < 128) b1s[tid] = bu1[tid];
    else if (tid < 192) b2s[tid - 128] = bu2[tid - 128];
    {
        const uint4* s1 = (const uint4*)U1h; const uint4* s2 = (const uint4*)U1l;
        uint4* d1 = (uint4*)sm; uint4* d2 = (uint4*)(sm + WB);
        for (int i = tid; i < WB / 16; i += 256) { d1[i] = s1[i]; d2[i] = s2[i]; }
    }

    {   // gather cat(obj, agg): thread quad per object
        int a = tid >> 2, h = tid & 3;
        int go = base + a;
        int gc = (go < nObj) ? go : 0;
        const float* src = ((h < 2) ? g_obj : g_agg) + (size_t)gc * HID + (h & 1) * 32;
        #pragma unroll
        for (int q = 0; q < 8; q++) {
            float4 v = *(const float4*)(src + q * 4);
            u32 h0, l0, h1, l1;
            split2(v.x, v.y, h0, l0);
            split2(v.z, v.w, h1, l1);
            u32 bo = (u32)(a * KP + h * 32 + q * 4) * 2;
            *(u64*)(xh_c + bo) = (u64)h0 | ((u64)h1 << 32);
            *(u64*)(xl_c + bo) = (u64)l0 | ((u64)l1 << 32);
        }
    }
    __syncthreads();

    float acc[4 * 2 * 4];
    #pragma unroll
    for (int i = 0; i < 32; i++) acc[i] = 0.f;
    warp_gemm<128, 128, 8>(XHa, XLa, WH, WL, warp, lane, acc);
    __syncthreads();

    // epilogue1 -> H in X planes; stage U2
    #pragma unroll
    for (int mt = 0; mt < 4; mt++)
        #pragma unroll
        for (int nt = 0; nt < 2; nt++) {
            float* d = acc + (mt * 2 + nt) * 4;
            int row = mt * 16 + (lane >> 2);
            int col = warp * 16 + nt * 8 + 2 * (lane & 3);
            u32 hh, ll;
            float x0 = fmaxf(d[0] + b1s[col], 0.f), x1 = fmaxf(d[1] + b1s[col + 1], 0.f);
            split2(x0, x1, hh, ll);
            *(u32*)(xh_c + (row * KP + col) * 2) = hh;
            *(u32*)(xl_c + (row * KP + col) * 2) = ll;
            float x2 = fmaxf(d[2] + b1s[col], 0.f), x3 = fmaxf(d[3] + b1s[col + 1], 0.f);
            split2(x2, x3, hh, ll);
            *(u32*)(xh_c + ((row + 8) * KP + col) * 2) = hh;
            *(u32*)(xl_c + ((row + 8) * KP + col) * 2) = ll;
        }
    {
        constexpr int WB2 = 64 * KP * 2;
        const uint4* s1 = (const uint4*)U2h; const uint4* s2 = (const uint4*)U2l;
        uint4* d1 = (uint4*)sm; uint4* d2 = (uint4*)(sm + WB);
        for (int i = tid; i < WB2 / 16; i += 256) { d1[i] = s1[i]; d2[i] = s2[i]; }
    }
    __syncthreads();

    #pragma unroll
    for (int i = 0; i < 16; i++) acc[i] = 0.f;
    warp_gemm<128, 64, 8>(XHa, XLa, WH, WL, warp, lane, acc);
    __syncthreads();

    // epilogue2 -> F (f32 [64][68])
    #pragma unroll
    for (int mt = 0; mt < 4; mt++) {
        float* d = acc + mt * 4;
        int row = mt * 16 + (lane >> 2);
        int col = warp * 8 + 2 * (lane & 3);
        *(float2*)(F + row * FP + col) =
            make_float2(d[0] + b2s[col], d[1] + b2s[col + 1]);
        *(float2*)(F + (row + 8) * FP + col) =
            make_float2(d[2] + b2s[col], d[3] + b2s[col + 1]);
    }
    __syncthreads();

    {   // write back obj rows
        int a = tid >> 2, h = tid & 3;
        int go = base + a;
        if (go < nObj) {
            float* dst = g_obj + (size_t)go * HID + h * 16;
            const float* f = F + a * FP + h * 16;
            #pragma unroll
            for (int q = 0; q < 4; q++)
                *(float4*)(dst + q * 4) = *(const float4*)(f + q * 4);
        }
    }
}

// ---------------------------------------------------------------------------
// layer-1 shortcut + small kernels
// ---------------------------------------------------------------------------
__global__ void zero_init_kernel(int nObj) {
    int i = blockIdx.x * 256 + threadIdx.x;
    if (i < nObj * HID)       g_obj[i] = 0.f;
    if (i < 6 * MAX_OBJ)      g_deg[i] = 0;
    if (i < MAX_GRAPHS * HID) g_pooled[i] = 0.f;
}
__global__ void zero_agg_kernel(int nObj) {
    int i = blockIdx.x * 256 + threadIdx.x;
    if (i < nObj * HID) g_agg[i] = 0.f;
}
__global__ void const_kernel(const float* b11, const float* w12, const float* b12,
                             const float* b21, const float* w22, const float* b22,
                             const float* b31, const float* w32, const float* b32) {
    int pred = blockIdx.x, j = threadIdx.x;
    const float *b1, *W2, *b2; int D, off;
    if (pred == 0)      { b1 = b11; W2 = w12; b2 = b12; D = 64;  off = 0;   }
    else if (pred == 1) { b1 = b21; W2 = w22; b2 = b22; D = 128; off = 64;  }
    else                { b1 = b31; W2 = w32; b2 = b32; D = 192; off = 192; }
    if (j < D) {
        float s = 0.f;
        for (int k = 0; k < D; k++) s = fmaf(fmaxf(b1[k], 0.f), W2[k * D + j], s);
        g_const[off + j] = s + b2[j];
    }
}
__global__ void deg_count_kernel(const int* __restrict__ ei, int n, int slotBase) {
    int s = blockIdx.y;
    int i = blockIdx.x * 256 + threadIdx.x;
    if (i < n) atomicAdd(&g_deg[(slotBase + s) * MAX_OBJ + ei[s * n + i]], 1);
}
__global__ void layer1_agg_kernel(int nObj) {
    int i = blockIdx.x * 256 + threadIdx.x;
    if (i >= nObj * HID) return;
    int o = i >> 6, c = i & 63;
    g_agg[i] = (float)g_deg[0 * MAX_OBJ + o] * g_const[c]
             + (float)g_deg[1 * MAX_OBJ + o] * g_const[64 + c]
             + (float)g_deg[2 * MAX_OBJ + o] * g_const[128 + c]
             + (float)g_deg[3 * MAX_OBJ + o] * g_const[192 + c]
             + (float)g_deg[4 * MAX_OBJ + o] * g_const[256 + c]
             + (float)g_deg[5 * MAX_OBJ + o] * g_const[320 + c];
}
__global__ void pool_kernel(const int* __restrict__ batch, int nObj) {
    int c = threadIdx.x;
    int base = blockIdx.x * 64;
    int end = min(base + 64, nObj);
    int cur = -1; float s = 0.f;
    for (int o = base; o < end; o++) {
        int b = batch[o];
        if (b != cur) {
            if (cur >= 0) atomicAdd(&g_pooled[cur * HID + c], s);
            cur = b; s = 0.f;
        }
        s += g_obj[(size_t)o * HID + c];
    }
    if (cur >= 0) atomicAdd(&g_pooled[cur * HID + c], s);
}
__global__ void readout_kernel(const float* __restrict__ w1, const float* __restrict__ b1,
                               const float* __restrict__ w2, const float* __restrict__ b2,
                               float* __restrict__ out) {
    __shared__ float p[64];
    __shared__ float red[4];
    int g = blockIdx.x, t = threadIdx.x;
    if (t < 64) p[t] = g_pooled[g * HID + t];
    __syncthreads();
    float acc = 0.f;
    #pragma unroll
    for (int k = 0; k < 64; k++) acc = fmaf(p[k], w1[k * 128 + t], acc);
    acc = fmaxf(acc + b1[t], 0.f) * w2[t];
    #pragma unroll
    for (int off = 16; off; off >>= 1) acc += __shfl_down_sync(0xffffffffu, acc, off);
    if ((t & 31) == 0) red[t >> 5] = acc;
    __syncthreads();
    if (t == 0) out[g] = red[0] + red[1] + red[2] + red[3] + b2[0];
}

// ---------------------------------------------------------------------------
extern "C" void kernel_launch(void* const* d_in, const int* in_sizes, int n_in,
                              void* d_out, int out_size) {
    const float* w_p1_1 = (const float*)d_in[4];
    const float* b_p1_1 = (const float*)d_in[5];
    const float* w_p1_2 = (const float*)d_in[6];
    const float* b_p1_2 = (const float*)d_in[7];
    const float* w_p2_1 = (const float*)d_in[8];
    const float* b_p2_1 = (const float*)d_in[9];
    const float* w_p2_2 = (const float*)d_in[10];
    const float* b_p2_2 = (const float*)d_in[11];
    const float* w_p3_1 = (const float*)d_in[12];
    const float* b_p3_1 = (const float*)d_in[13];
    const float* w_p3_2 = (const float*)d_in[14];
    const float* b_p3_2 = (const float*)d_in[15];
    const float* w_u1   = (const float*)d_in[16];
    const float* b_u1   = (const float*)d_in[17];
    const float* w_u2   = (const float*)d_in[18];
    const float* b_u2   = (const float*)d_in[19];
    const float* w_r1   = (const float*)d_in[20];
    const float* b_r1   = (const float*)d_in[21];
    const float* w_r2   = (const float*)d_in[22];
    const float* b_r2   = (const float*)d_in[23];
    const int*   ei_p1  = (const int*)d_in[24];
    const int*   ei_p2  = (const int*)d_in[25];
    const int*   ei_p3  = (const int*)d_in[26];
    const int*   batch  = (const int*)d_in[27];

    const int nObj = in_sizes[0];
    const int nP1  = in_sizes[24];
    const int nP2  = in_sizes[25] / 2;
    const int nP3  = in_sizes[26] / 3;
    const int nGraphs = out_size;
    float* out = (float*)d_out;

    u16* wb = nullptr;
    cudaGetSymbolAddress((void**)&wb, g_wbuf);

    const int smem1 = 2 * (64 * 72 * 2)   + 2 * (64 * 72 * 2)   + 8 * 64  + 1 * 64 * 4;
    const int smem2 = 2 * (128 * 136 * 2) + 2 * (64 * 136 * 2)  + 8 * 128 + 2 * 64 * 4;
    const int smem3 = 2 * (192 * 200 * 2) + 2 * (64 * 200 * 2)  + 8 * 192 + 3 * 64 * 4;
    const int smemU = 2 * (128 * 136 * 2) + 2 * (64 * 136 * 2)  + 128 * 4 + 64 * 4;
    cudaFuncSetAttribute(pred_mma_kernel<1>, cudaFuncAttributeMaxDynamicSharedMemorySize, smem1);
    cudaFuncSetAttribute(pred_mma_kernel<2>, cudaFuncAttributeMaxDynamicSharedMemorySize, smem2);
    cudaFuncSetAttribute(pred_mma_kernel<3>, cudaFuncAttributeMaxDynamicSharedMemorySize, smem3);
    cudaFuncSetAttribute(update_mma_kernel, cudaFuncAttributeMaxDynamicSharedMemorySize, smemU);

    prep_weight_kernel<<<(64 * 72 + 255) / 256, 256>>>(w_p1_1, wb + 0,      wb + 4608,   64, 64);
    prep_weight_kernel<<<(64 * 72 + 255) / 256, 256>>>(w_p1_2, wb + 9216,   wb + 13824,  64, 64);
    prep_weight_kernel<<<(128 * 136 + 255) / 256, 256>>>(w_p2_1, wb + 18432, wb + 35840, 128, 128);
    prep_weight_kernel<<<(128 * 136 + 255) / 256, 256>>>(w_p2_2, wb + 53248, wb + 70656, 128, 128);
    prep_weight_kernel<<<(192 * 200 + 255) / 256, 256>>>(w_p3_1, wb + 88064, wb + 126464, 192, 192);
    prep_weight_kernel<<<(192 * 200 + 255) / 256, 256>>>(w_p3_2, wb + 164864, wb + 203264, 192, 192);
    prep_weight_kernel<<<(128 * 136 + 255) / 256, 256>>>(w_u1, wb + 241664, wb + 259072, 128, 128);
    prep_weight_kernel<<<(64 * 136 + 255) / 256, 256>>>(w_u2, wb + 276480, wb + 285184, 128, 64);

    const int bObj = (nObj + 63) / 64;
    const int bP1  = (nP1 + 63) / 64;
    const int bP2  = (nP2 + 63) / 64;
    const int bP3  = (nP3 + 63) / 64;

    int zn = nObj * HID; if (6 * MAX_OBJ > zn) zn = 6 * MAX_OBJ;
    zero_init_kernel<<<(zn + 255) / 256, 256>>>(nObj);
    const_kernel<<<3, 192>>>(b_p1_1, w_p1_2, b_p1_2,
                             b_p2_1, w_p2_2, b_p2_2,
                             b_p3_1, w_p3_2, b_p3_2);
    deg_count_kernel<<<dim3((nP1 + 255) / 256, 1), 256>>>(ei_p1, nP1, 0);
    deg_count_kernel<<<dim3((nP2 + 255) / 256, 2), 256>>>(ei_p2, nP2, 1);
    deg_count_kernel<<<dim3((nP3 + 255) / 256, 3), 256>>>(ei_p3, nP3, 3);
    layer1_agg_kernel<<<(nObj * HID + 255) / 256, 256>>>(nObj);
    update_mma_kernel<<<bObj, 256, smemU>>>(wb + 241664, wb + 259072,
                                            wb + 276480, wb + 285184, b_u1, b_u2, nObj);

    for (int layer = 1; layer < 3; layer++) {
        zero_agg_kernel<<<(nObj * HID + 255) / 256, 256>>>(nObj);
        pred_mma_kernel<1><<<bP1, 256, smem1>>>(ei_p1, nP1, wb + 0, wb + 4608,
                                                wb + 9216, wb + 13824, b_p1_1, b_p1_2);
        pred_mma_kernel<2><<<bP2, 256, smem2>>>(ei_p2, nP2, wb + 18432, wb + 35840,
                                                wb + 53248, wb + 70656, b_p2_1, b_p2_2);
        pred_mma_kernel<3><<<bP3, 256, smem3>>>(ei_p3, nP3, wb + 88064, wb + 126464,
                                                wb + 164864, wb + 203264, b_p3_1, b_p3_2);
        update_mma_kernel<<<bObj, 256, smemU>>>(wb + 241664, wb + 259072,
                                                wb + 276480, wb + 285184, b_u1, b_u2, nObj);
    }

    pool_kernel<<<bObj, 64>>>(batch, nObj);
    readout_kernel<<<nGraphs, 128>>>(w_r1, b_r1, w_r2, b_r2, out);
}